// round 12
// baseline (speedup 1.0000x reference)
#include <cuda_runtime.h>
#include <cstdint>

#define NN 50000
#define DD 64
#define EE 800000
#define SCAN_BS 1024
#define NBLK ((NN + SCAN_BS - 1) / SCAN_BS)   // 49

// Scratch (no cudaMalloc allowed)
__device__ float g_H[NN * DD];
__device__ int   g_counts[NN];       // zero-init at load; reset by scan3 each run
__device__ int   g_cursor[NN];
__device__ int2  g_ofscnt[NN];       // (offset, count) packed for gather
__device__ int   g_offsets_tmp[NN];  // block-local exclusive offsets (scan1)
__device__ int   g_bsum[64];
__device__ int2  g_recs[EE];         // (src, bitcast(weight)) binned by dst

// ---------------------------------------------------------------------------
// edge_index dtype is ambiguous (jnp.int64 without x64 -> int32); detect at
// runtime: int64 values < 50000 have all-zero odd 32-bit words.
// ---------------------------------------------------------------------------
__device__ __forceinline__ bool detect_i64(const int* __restrict__ ei32) {
    return (ei32[1] | ei32[3] | ei32[5] | ei32[7] |
            ei32[9] | ei32[11] | ei32[13] | ei32[15]) == 0;
}

// ---------------------------------------------------------------------------
// 2 edges per thread, vectorized index loads.
__global__ __launch_bounds__(256) void hist_kernel(const int* __restrict__ ei32) {
    int t = blockIdx.x * blockDim.x + threadIdx.x;
    if (t >= EE / 2) return;
    bool is64 = detect_i64(ei32);
    int d0, d1;
    if (is64) {
        const longlong2* p = (const longlong2*)(ei32 + 2 * EE);
        longlong2 v = p[t];
        d0 = (int)v.x; d1 = (int)v.y;
    } else {
        const int2* p = (const int2*)(ei32 + EE);
        int2 v = p[t];
        d0 = v.x; d1 = v.y;
    }
    atomicAdd(&g_counts[d0], 1);
    atomicAdd(&g_counts[d1], 1);
}

// Block-wide inclusive scan (Hillis-Steele): block-exclusive offsets + block sums.
__global__ __launch_bounds__(SCAN_BS) void scan1_kernel() {
    __shared__ int s[SCAN_BS];
    int i = blockIdx.x * SCAN_BS + threadIdx.x;
    int v = (i < NN) ? g_counts[i] : 0;
    s[threadIdx.x] = v;
    __syncthreads();
#pragma unroll
    for (int off = 1; off < SCAN_BS; off <<= 1) {
        int y = (threadIdx.x >= off) ? s[threadIdx.x - off] : 0;
        __syncthreads();
        s[threadIdx.x] += y;
        __syncthreads();
    }
    if (i < NN) g_offsets_tmp[i] = s[threadIdx.x] - v;   // exclusive within block
    if (threadIdx.x == SCAN_BS - 1) g_bsum[blockIdx.x] = s[SCAN_BS - 1];
}

// Apply cross-block prefix (masked parallel load + warp shfl-reduce; no serial
// gmem loop). Also RESETS g_counts for the next graph replay (hist needs zeros).
__global__ __launch_bounds__(256) void scan3_kernel() {
    __shared__ int s_prefix;
    int lane = threadIdx.x & 31;
    if (threadIdx.x < 32) {
        int sb = blockIdx.x >> 2;   // uniform: 256 | 1024
        int v = (lane < sb && lane < NBLK) ? g_bsum[lane] : 0;
        if (lane + 32 < sb && lane + 32 < NBLK) v += g_bsum[lane + 32];
#pragma unroll
        for (int off = 16; off > 0; off >>= 1)
            v += __shfl_xor_sync(0xffffffffu, v, off);
        if (lane == 0) s_prefix = v;
    }
    __syncthreads();
    int i = blockIdx.x * blockDim.x + threadIdx.x;
    if (i < NN) {
        int o = g_offsets_tmp[i] + s_prefix;
        int c = g_counts[i];
        g_ofscnt[i] = make_int2(o, c);
        g_cursor[i] = o;
        g_counts[i] = 0;             // reset for next replay
    }
}

// 2 edges per thread, vectorized loads.
__global__ __launch_bounds__(256) void fill_kernel(const int* __restrict__ ei32,
                                                   const float* __restrict__ ew) {
    int t = blockIdx.x * blockDim.x + threadIdx.x;
    if (t >= EE / 2) return;
    bool is64 = detect_i64(ei32);
    int s0, s1, d0, d1;
    if (is64) {
        const longlong2* ps = (const longlong2*)ei32;
        const longlong2* pd = (const longlong2*)(ei32 + 2 * EE);
        longlong2 vs = ps[t];
        longlong2 vd = pd[t];
        s0 = (int)vs.x; s1 = (int)vs.y;
        d0 = (int)vd.x; d1 = (int)vd.y;
    } else {
        const int2* ps = (const int2*)ei32;
        const int2* pd = (const int2*)(ei32 + EE);
        int2 vs = ps[t];
        int2 vd = pd[t];
        s0 = vs.x; s1 = vs.y;
        d0 = vd.x; d1 = vd.y;
    }
    float2 w = ((const float2*)ew)[t];
    int p0 = atomicAdd(&g_cursor[d0], 1);
    g_recs[p0] = make_int2(s0, __float_as_int(w.x));
    int p1 = atomicAdd(&g_cursor[d1], 1);
    g_recs[p1] = make_int2(s1, __float_as_int(w.y));
}

// ---------------------------------------------------------------------------
// Fused gather + dual-GEMM + bias + sigmoid.
//   AGG(tile) = scatter_add(Xv[src]*w -> dst) for the block's 64 rows (smem)
//   out(tile) = sigmoid(AGG @ Wrel^T + R @ Wroot^T + bias)
// 256 threads, 64-row tile.
// Phase 1: warp w gathers nodes row0+w*8 .. +7 (half-warp edge pairs, x2
//   unrolled for MLP; lane j<16 owns float4 j) into smem As.
// Phase 2: thread (cg=tid&7, rg=tid>>3) computes 8 cols x 2 rows.
//   A from smem (broadcast LDS), R from gmem (8 same-address lanes coalesce),
//   weights in smem with 8x8 slot transpose (conflict-free 128B LDS).
// smem = 16K + 16K + 16K = 48KB exactly.
// ---------------------------------------------------------------------------
__global__ __launch_bounds__(256) void fused_gather_gemm_kernel(
    const float4* __restrict__ Xv,    // gather source, [NN,16] float4 rows
    const float*  __restrict__ R,     // root input
    const float*  __restrict__ Wrel,  // [64,64] row-major [out][in]
    const float*  __restrict__ Wroot,
    const float* __restrict__ b0, const float* __restrict__ b1,
    const float* __restrict__ b2, const float* __restrict__ b3,
    float* __restrict__ out)
{
    __shared__ float4 WrS[16 * 64];   // 16KB, packed [kq][slot]
    __shared__ float4 WoS[16 * 64];   // 16KB
    __shared__ float4 As[64 * 16];    // 16KB gathered AGG tile

    int tid = threadIdx.x;
    int row0 = blockIdx.x * 64;

    // Weight load + transpose-pack (coalesced gmem reads)
    const float4* Wrel4  = (const float4*)Wrel;
    const float4* Wroot4 = (const float4*)Wroot;
    for (int idx = tid; idx < 1024; idx += 256) {
        int c = idx >> 4, kq = idx & 15;
        int slot = kq * 64 + (c & 7) * 8 + (c >> 3);
        WrS[slot] = Wrel4[idx];
        WoS[slot] = Wroot4[idx];
    }

    // ---- Phase 1: gather 8 nodes per warp into As ----
    {
        int warp = tid >> 5;
        int lane = tid & 31;
        int half = lane >> 4;
        int j    = lane & 15;
#pragma unroll 1
        for (int k = 0; k < 8; k++) {
            int node = row0 + warp * 8 + k;
            float4 acc = make_float4(0.f, 0.f, 0.f, 0.f);
            if (node < NN) {
                int2 oc   = g_ofscnt[node];
                int start = oc.x;
                int cnt   = oc.y;
                int i = half;
                for (; i + 2 < cnt; i += 4) {
                    int2  rec0 = g_recs[start + i];
                    int2  rec1 = g_recs[start + i + 2];
                    float4 x0  = Xv[rec0.x * 16 + j];
                    float4 x1  = Xv[rec1.x * 16 + j];
                    float w0   = __int_as_float(rec0.y);
                    float w1   = __int_as_float(rec1.y);
                    acc.x += x0.x * w0;  acc.y += x0.y * w0;
                    acc.z += x0.z * w0;  acc.w += x0.w * w0;
                    acc.x += x1.x * w1;  acc.y += x1.y * w1;
                    acc.z += x1.z * w1;  acc.w += x1.w * w1;
                }
                if (i < cnt) {
                    int2  rec = g_recs[start + i];
                    float w   = __int_as_float(rec.y);
                    float4 x  = Xv[rec.x * 16 + j];
                    acc.x += x.x * w;  acc.y += x.y * w;
                    acc.z += x.z * w;  acc.w += x.w * w;
                }
            }
            acc.x += __shfl_down_sync(0xffffffffu, acc.x, 16);
            acc.y += __shfl_down_sync(0xffffffffu, acc.y, 16);
            acc.z += __shfl_down_sync(0xffffffffu, acc.z, 16);
            acc.w += __shfl_down_sync(0xffffffffu, acc.w, 16);
            if (half == 0) As[(warp * 8 + k) * 16 + j] = acc;
        }
    }
    __syncthreads();

    // ---- Phase 2: GEMM. Thread: 8 cols (cg) x 2 rows (rg) ----
    int cg = tid & 7;
    int rg = tid >> 3;          // 0..31
    int rowA = rg * 2;          // local row in tile
    int row  = row0 + rowA;

    float acc[8][2];
#pragma unroll
    for (int i = 0; i < 8; i++)
#pragma unroll
        for (int t = 0; t < 2; t++) acc[i][t] = 0.f;

    const float4* R4 = (const float4*)R;
    bool full = (row + 1 < NN);

#pragma unroll 2
    for (int kq = 0; kq < 16; kq++) {
        float4 a[2], r[2];
#pragma unroll
        for (int t = 0; t < 2; t++) {
            a[t] = As[(rowA + t) * 16 + kq];
            if (full || row + t < NN) {
                r[t] = R4[(row + t) * 16 + kq];
            } else {
                r[t] = make_float4(0.f, 0.f, 0.f, 0.f);
            }
        }
#pragma unroll
        for (int i = 0; i < 8; i++) {
            float4 wr = WrS[kq * 64 + i * 8 + cg];   // lanes cg=0..7 contiguous
            float4 wo = WoS[kq * 64 + i * 8 + cg];
#pragma unroll
            for (int t = 0; t < 2; t++) {
                acc[i][t] += a[t].x * wr.x + a[t].y * wr.y
                           + a[t].z * wr.z + a[t].w * wr.w
                           + r[t].x * wo.x + r[t].y * wo.y
                           + r[t].z * wo.z + r[t].w * wo.w;
            }
        }
    }

    float bias[8];
#pragma unroll
    for (int i = 0; i < 8; i++) {
        int c = cg * 8 + i;
        bias[i] = b0[c] + b1[c];
        if (b2 != nullptr) bias[i] += b2[c] + b3[c];
    }

#pragma unroll
    for (int t = 0; t < 2; t++) {
        if (row + t < NN) {
            float4 o0, o1;
            o0.x = 1.f / (1.f + __expf(-(acc[0][t] + bias[0])));
            o0.y = 1.f / (1.f + __expf(-(acc[1][t] + bias[1])));
            o0.z = 1.f / (1.f + __expf(-(acc[2][t] + bias[2])));
            o0.w = 1.f / (1.f + __expf(-(acc[3][t] + bias[3])));
            o1.x = 1.f / (1.f + __expf(-(acc[4][t] + bias[4])));
            o1.y = 1.f / (1.f + __expf(-(acc[5][t] + bias[5])));
            o1.z = 1.f / (1.f + __expf(-(acc[6][t] + bias[6])));
            o1.w = 1.f / (1.f + __expf(-(acc[7][t] + bias[7])));
            float4* op = (float4*)&out[(row + t) * DD + cg * 8];
            op[0] = o0;
            op[1] = o1;
        }
    }
}

// ---------------------------------------------------------------------------
extern "C" void kernel_launch(void* const* d_in, const int* in_sizes, int n_in,
                              void* d_out, int out_size)
{
    const float* X      = (const float*)d_in[0];
    const int*   ei     = (const int*)  d_in[1];   // raw; dtype auto-detected
    const float* ew     = (const float*)d_in[2];
    const float* Wrel1  = (const float*)d_in[3];
    const float* brel1  = (const float*)d_in[4];
    const float* Wroot1 = (const float*)d_in[5];
    const float* broot1 = (const float*)d_in[6];
    const float* brel2  = (const float*)d_in[8];
    const float* broot2 = (const float*)d_in[10];
    const float* Wrel3  = (const float*)d_in[11];
    const float* brel3  = (const float*)d_in[12];
    const float* Wroot3 = (const float*)d_in[13];
    const float* broot3 = (const float*)d_in[14];
    float* out = (float*)d_out;

    float* h;
    cudaGetSymbolAddress((void**)&h, g_H);

    // --- CSR build (counts pre-zeroed: load-time init / scan3 reset) ---
    hist_kernel<<<(EE / 2 + 255) / 256, 256>>>(ei);
    scan1_kernel<<<NBLK, SCAN_BS>>>();
    scan3_kernel<<<(NN + 255) / 256, 256>>>();
    fill_kernel<<<(EE / 2 + 255) / 256, 256>>>(ei, ew);

    // --- pass 1: H = sigmoid(gather(X)@Wrel1^T + X@Wroot1^T + biases) ---
    fused_gather_gemm_kernel<<<(NN + 63) / 64, 256>>>(
        (const float4*)X, X, Wrel1, Wroot1, brel1, broot1, brel2, broot2, h);

    // --- pass 2: out = sigmoid(gather(H)@Wrel3^T + H@Wroot3^T + biases) ---
    fused_gather_gemm_kernel<<<(NN + 63) / 64, 256>>>(
        (const float4*)h, h, Wrel3, Wroot3, brel3, broot3, nullptr, nullptr, out);
}

// round 14
// speedup vs baseline: 1.6096x; 1.6096x over previous
#include <cuda_runtime.h>
#include <cstdint>

#define NN 50000
#define DD 64
#define EE 800000
#define SCAN_BS 1024
#define NBLK ((NN + SCAN_BS - 1) / SCAN_BS)   // 49

// Scratch (no cudaMalloc allowed)
__device__ float g_AGG[NN * DD];
__device__ float g_H[NN * DD];
__device__ int   g_counts[NN];       // zero-init at load; reset by scan3 each run
__device__ int   g_cursor[NN];
__device__ int2  g_ofscnt[NN];       // (offset, count) packed for gather
__device__ int   g_offsets_tmp[NN];
__device__ int   g_bsum[64];
__device__ int2  g_recs[EE];         // (src, bitcast(weight)) binned by dst

// ---------------------------------------------------------------------------
// edge_index dtype is ambiguous (jnp.int64 without x64 -> int32); detect at
// runtime: int64 values < 50000 have all-zero odd 32-bit words.
// ---------------------------------------------------------------------------
__device__ __forceinline__ bool detect_i64(const int* __restrict__ ei32) {
    return (ei32[1] | ei32[3] | ei32[5] | ei32[7] |
            ei32[9] | ei32[11] | ei32[13] | ei32[15]) == 0;
}

// tf32 helpers
__device__ __forceinline__ unsigned tf32_hi(float f) {
    unsigned u;
    asm("cvt.rna.tf32.f32 %0, %1;" : "=r"(u) : "f"(f));
    return u;
}
__device__ __forceinline__ void tf32_split(float f, unsigned& hi, unsigned& lo) {
    hi = tf32_hi(f);
    lo = tf32_hi(f - __uint_as_float(hi));
}
__device__ __forceinline__ void mma8(float* c, const unsigned* a,
                                     unsigned b0, unsigned b1) {
    asm("mma.sync.aligned.m16n8k8.row.col.f32.tf32.tf32.f32 "
        "{%0,%1,%2,%3},{%4,%5,%6,%7},{%8,%9},{%0,%1,%2,%3};"
        : "+f"(c[0]), "+f"(c[1]), "+f"(c[2]), "+f"(c[3])
        : "r"(a[0]), "r"(a[1]), "r"(a[2]), "r"(a[3]), "r"(b0), "r"(b1));
}

// ---------------------------------------------------------------------------
// 2 edges per thread, vectorized index loads.
__global__ __launch_bounds__(256) void hist_kernel(const int* __restrict__ ei32) {
    int t = blockIdx.x * blockDim.x + threadIdx.x;
    if (t >= EE / 2) return;
    bool is64 = detect_i64(ei32);
    int d0, d1;
    if (is64) {
        const longlong2* p = (const longlong2*)(ei32 + 2 * EE);
        longlong2 v = p[t];
        d0 = (int)v.x; d1 = (int)v.y;
    } else {
        const int2* p = (const int2*)(ei32 + EE);
        int2 v = p[t];
        d0 = v.x; d1 = v.y;
    }
    atomicAdd(&g_counts[d0], 1);
    atomicAdd(&g_counts[d1], 1);
}

__global__ __launch_bounds__(SCAN_BS) void scan1_kernel() {
    __shared__ int s[SCAN_BS];
    int i = blockIdx.x * SCAN_BS + threadIdx.x;
    int v = (i < NN) ? g_counts[i] : 0;
    s[threadIdx.x] = v;
    __syncthreads();
#pragma unroll
    for (int off = 1; off < SCAN_BS; off <<= 1) {
        int y = (threadIdx.x >= off) ? s[threadIdx.x - off] : 0;
        __syncthreads();
        s[threadIdx.x] += y;
        __syncthreads();
    }
    if (i < NN) g_offsets_tmp[i] = s[threadIdx.x] - v;
    if (threadIdx.x == SCAN_BS - 1) g_bsum[blockIdx.x] = s[SCAN_BS - 1];
}

// Cross-block prefix (masked parallel load + warp shfl-reduce). Also resets
// g_counts for the next graph replay.
__global__ __launch_bounds__(256) void scan3_kernel() {
    __shared__ int s_prefix;
    int lane = threadIdx.x & 31;
    if (threadIdx.x < 32) {
        int sb = blockIdx.x >> 2;   // uniform: 256 | 1024
        int v = (lane < sb && lane < NBLK) ? g_bsum[lane] : 0;
        if (lane + 32 < sb && lane + 32 < NBLK) v += g_bsum[lane + 32];
#pragma unroll
        for (int off = 16; off > 0; off >>= 1)
            v += __shfl_xor_sync(0xffffffffu, v, off);
        if (lane == 0) s_prefix = v;
    }
    __syncthreads();
    int i = blockIdx.x * blockDim.x + threadIdx.x;
    if (i < NN) {
        int o = g_offsets_tmp[i] + s_prefix;
        int c = g_counts[i];
        g_ofscnt[i] = make_int2(o, c);
        g_cursor[i] = o;
        g_counts[i] = 0;
    }
}

__global__ __launch_bounds__(256) void fill_kernel(const int* __restrict__ ei32,
                                                   const float* __restrict__ ew) {
    int t = blockIdx.x * blockDim.x + threadIdx.x;
    if (t >= EE / 2) return;
    bool is64 = detect_i64(ei32);
    int s0, s1, d0, d1;
    if (is64) {
        const longlong2* ps = (const longlong2*)ei32;
        const longlong2* pd = (const longlong2*)(ei32 + 2 * EE);
        longlong2 vs = ps[t];
        longlong2 vd = pd[t];
        s0 = (int)vs.x; s1 = (int)vs.y;
        d0 = (int)vd.x; d1 = (int)vd.y;
    } else {
        const int2* ps = (const int2*)ei32;
        const int2* pd = (const int2*)(ei32 + EE);
        int2 vs = ps[t];
        int2 vd = pd[t];
        s0 = vs.x; s1 = vs.y;
        d0 = vd.x; d1 = vd.y;
    }
    float2 w = ((const float2*)ew)[t];
    int p0 = atomicAdd(&g_cursor[d0], 1);
    g_recs[p0] = make_int2(s0, __float_as_int(w.x));
    int p1 = atomicAdd(&g_cursor[d1], 1);
    g_recs[p1] = make_int2(s1, __float_as_int(w.y));
}

// ---------------------------------------------------------------------------
// Gather: one warp per destination node, no atomics (measured-good, unchanged).
// ---------------------------------------------------------------------------
__global__ __launch_bounds__(256) void gather_kernel(const float4* __restrict__ Xv,
                                                     float4* __restrict__ agg) {
    int warp = (blockIdx.x * blockDim.x + threadIdx.x) >> 5;
    if (warp >= NN) return;
    int lane = threadIdx.x & 31;
    int half = lane >> 4;
    int j    = lane & 15;

    int2 oc   = g_ofscnt[warp];
    int start = oc.x;
    int cnt   = oc.y;

    float4 acc = make_float4(0.f, 0.f, 0.f, 0.f);
    int i = half;
    for (; i + 2 < cnt; i += 4) {
        int2  rec0 = g_recs[start + i];
        int2  rec1 = g_recs[start + i + 2];
        float4 x0  = Xv[rec0.x * 16 + j];
        float4 x1  = Xv[rec1.x * 16 + j];
        float w0   = __int_as_float(rec0.y);
        float w1   = __int_as_float(rec1.y);
        acc.x += x0.x * w0;  acc.y += x0.y * w0;
        acc.z += x0.z * w0;  acc.w += x0.w * w0;
        acc.x += x1.x * w1;  acc.y += x1.y * w1;
        acc.z += x1.z * w1;  acc.w += x1.w * w1;
    }
    if (i < cnt) {
        int2  rec = g_recs[start + i];
        float w   = __int_as_float(rec.y);
        float4 x  = Xv[rec.x * 16 + j];
        acc.x += x.x * w;  acc.y += x.y * w;
        acc.z += x.z * w;  acc.w += x.w * w;
    }
    acc.x += __shfl_down_sync(0xffffffffu, acc.x, 16);
    acc.y += __shfl_down_sync(0xffffffffu, acc.y, 16);
    acc.z += __shfl_down_sync(0xffffffffu, acc.z, 16);
    acc.w += __shfl_down_sync(0xffffffffu, acc.w, 16);
    if (half == 0) agg[warp * 16 + j] = acc;
}

// ---------------------------------------------------------------------------
// Tensor-core dual-GEMM + bias + sigmoid via 3xTF32 mma.m16n8k8.
//   out = sigmoid(A @ Wrel^T + R @ Wroot^T + bias),  error ~2^-21/product.
// Block: 256 threads (8 warps) x 16 rows/warp = 128-row tile. grid=391.
// B fragments pre-swizzled in smem at pack time: WF[mat*64 + nt*8 + ks][lane]
// = uint4{hi(W[n][k]), lo(W[n][k]), hi(W[n][k+4]), lo(W[n][k+4])} with
// n = nt*8 + lane/4, k = ks*8 + lane%4  -> frag load = one conflict-free
// LDS.128. A fragments load directly from gmem (quad = contiguous 32B sector)
// and are hi/lo split in registers.
// ---------------------------------------------------------------------------
__global__ __launch_bounds__(256) void gemm_tf32_kernel(
    const float* __restrict__ A,
    const float* __restrict__ R,
    const float* __restrict__ Wrel,   // [64,64] row-major [out][in]
    const float* __restrict__ Wroot,
    const float* __restrict__ b0, const float* __restrict__ b1,
    const float* __restrict__ b2, const float* __restrict__ b3,
    float* __restrict__ out)
{
    __shared__ uint4 WF[128 * 32];    // 32KB: 2 mats x 64 frags x 32 lanes
    __shared__ float bias_s[64];

    int tid = threadIdx.x;

    // Bias precompute
    if (tid < 64) {
        float b = b0[tid] + b1[tid];
        if (b2 != nullptr) b += b2[tid] + b3[tid];
        bias_s[tid] = b;
    }

    // Pack B fragments (W is 16KB, L1/L2-cached; scattered 4B reads OK)
    for (int idx = tid; idx < 4096; idx += 256) {
        int lane = idx & 31;
        int frag = idx >> 5;          // 0..127
        int mat  = frag >> 6;
        int rem  = frag & 63;
        int nt   = rem >> 3;
        int ks   = rem & 7;
        int n = nt * 8 + (lane >> 2);
        int k = ks * 8 + (lane & 3);
        const float* W = mat ? Wroot : Wrel;
        unsigned h0, l0, h1, l1;
        tf32_split(W[n * 64 + k],     h0, l0);
        tf32_split(W[n * 64 + k + 4], h1, l1);
        WF[idx] = make_uint4(h0, l0, h1, l1);
    }
    __syncthreads();

    int wid  = tid >> 5;
    int lane = tid & 31;
    int m0   = blockIdx.x * 128 + wid * 16;
    int r0   = m0 + (lane >> 2);
    int r1   = r0 + 8;
    bool v0 = (r0 < NN), v1 = (r1 < NN);

    float acc[8][4];
#pragma unroll
    for (int nt = 0; nt < 8; nt++)
#pragma unroll
        for (int i = 0; i < 4; i++) acc[nt][i] = 0.f;

#pragma unroll
    for (int mat = 0; mat < 2; mat++) {
        const float* S = mat ? R : A;
#pragma unroll
        for (int ks = 0; ks < 8; ks++) {
            int c0 = ks * 8 + (lane & 3);
            // A fragment: {[r0,c0],[r1,c0],[r0,c0+4],[r1,c0+4]}
            float f0 = v0 ? S[r0 * 64 + c0]     : 0.f;
            float f1 = v1 ? S[r1 * 64 + c0]     : 0.f;
            float f2 = v0 ? S[r0 * 64 + c0 + 4] : 0.f;
            float f3 = v1 ? S[r1 * 64 + c0 + 4] : 0.f;
            unsigned ahi[4], alo[4];
            tf32_split(f0, ahi[0], alo[0]);
            tf32_split(f1, ahi[1], alo[1]);
            tf32_split(f2, ahi[2], alo[2]);
            tf32_split(f3, ahi[3], alo[3]);
#pragma unroll
            for (int nt = 0; nt < 8; nt++) {
                uint4 b = WF[((mat << 6) + nt * 8 + ks) * 32 + lane];
                mma8(acc[nt], ahi, b.x, b.z);   // hi*hi
                mma8(acc[nt], ahi, b.y, b.w);   // hi*lo
                mma8(acc[nt], alo, b.x, b.z);   // lo*hi
            }
        }
    }

    // Epilogue: c-frag layout rows {r0, r1}, cols nt*8 + (lane&3)*2 + {0,1}
#pragma unroll
    for (int nt = 0; nt < 8; nt++) {
        int n0 = nt * 8 + (lane & 3) * 2;
        float ba = bias_s[n0], bb = bias_s[n0 + 1];
        if (v0) {
            float2 o;
            o.x = 1.f / (1.f + __expf(-(acc[nt][0] + ba)));
            o.y = 1.f / (1.f + __expf(-(acc[nt][1] + bb)));
            *(float2*)&out[r0 * 64 + n0] = o;
        }
        if (v1) {
            float2 o;
            o.x = 1.f / (1.f + __expf(-(acc[nt][2] + ba)));
            o.y = 1.f / (1.f + __expf(-(acc[nt][3] + bb)));
            *(float2*)&out[r1 * 64 + n0] = o;
        }
    }
}

// ---------------------------------------------------------------------------
extern "C" void kernel_launch(void* const* d_in, const int* in_sizes, int n_in,
                              void* d_out, int out_size)
{
    const float* X      = (const float*)d_in[0];
    const int*   ei     = (const int*)  d_in[1];   // raw; dtype auto-detected
    const float* ew     = (const float*)d_in[2];
    const float* Wrel1  = (const float*)d_in[3];
    const float* brel1  = (const float*)d_in[4];
    const float* Wroot1 = (const float*)d_in[5];
    const float* broot1 = (const float*)d_in[6];
    const float* brel2  = (const float*)d_in[8];
    const float* broot2 = (const float*)d_in[10];
    const float* Wrel3  = (const float*)d_in[11];
    const float* brel3  = (const float*)d_in[12];
    const float* Wroot3 = (const float*)d_in[13];
    const float* broot3 = (const float*)d_in[14];
    float* out = (float*)d_out;

    float *agg, *h;
    cudaGetSymbolAddress((void**)&agg, g_AGG);
    cudaGetSymbolAddress((void**)&h,   g_H);

    // --- CSR build (counts pre-zeroed: load-time init / scan3 reset) ---
    hist_kernel<<<(EE / 2 + 255) / 256, 256>>>(ei);
    scan1_kernel<<<NBLK, SCAN_BS>>>();
    scan3_kernel<<<(NN + 255) / 256, 256>>>();
    fill_kernel<<<(EE / 2 + 255) / 256, 256>>>(ei, ew);

    // --- pass 1 ---
    gather_kernel<<<(NN * 32 + 255) / 256, 256>>>((const float4*)X, (float4*)agg);
    gemm_tf32_kernel<<<(NN + 127) / 128, 256>>>(
        agg, X, Wrel1, Wroot1, brel1, broot1, brel2, broot2, h);

    // --- pass 2 ---
    gather_kernel<<<(NN * 32 + 255) / 256, 256>>>((const float4*)h, (float4*)agg);
    gemm_tf32_kernel<<<(NN + 127) / 128, 256>>>(
        agg, h, Wrel3, Wroot3, brel3, broot3, nullptr, nullptr, out);
}